// round 4
// baseline (speedup 1.0000x reference)
#include <cuda_runtime.h>

#define BB    8
#define NPTS  4096
#define KNN   20
#define TOTPTS (BB*NPTS)

// ---------------- static device scratch (sanctioned workaround) ----------------
static __device__ float g_h  [TOTPTS*64];   // features after conv1+conv2, (B,N,64)
static __device__ float g_nh [TOTPTS];      // ||h||^2
static __device__ float g_nx [TOTPTS];      // ||x||^2
static __device__ int   g_idx1[TOTPTS*KNN];
static __device__ int   g_idx2[TOTPTS*KNN];
static __device__ float g_a  [TOTPTS*64];   // (Wc-Wd)@h
static __device__ float g_u  [TOTPTS*64];   // Wd@h
static __device__ float g_hdg[TOTPTS*64];   // after dg branch max
static __device__ float g_p2 [TOTPTS*64];   // sn-branch per-point MLP output
static __device__ float g_hsn[TOTPTS*64];   // after sn gather-max (then conv3 in-place)
static __device__ float g_h4 [TOTPTS*128];  // after conv4

__device__ __forceinline__ float lrelu(float v){ return fmaxf(v, 0.01f*v); }

// pointer selectors (avoid host-side symbol lookups)
__device__ __forceinline__ const float* pconv_in(int sel){
    switch(sel){ case 0: return g_h; case 1: return g_hdg; case 2: return g_p2;
                 case 3: return g_hsn; default: return g_hsn; }
}
__device__ __forceinline__ float* pconv_out(int sel){
    switch(sel){ case 0: return g_h; case 1: return g_p2; case 2: return g_p2;
                 case 3: return g_hsn; default: return g_h4; }
}

// ---------------- conv1: x(B,N,3) -> g_h (64ch), one thread per (point,channel) ----------------
__global__ void k_conv1(const float* __restrict__ x, const float* __restrict__ w,
                        const float* __restrict__ g, const float* __restrict__ b)
{
    __shared__ float sw[192], sg[64], sb[64];
    int t = threadIdx.x;
    if (t < 192) sw[t] = w[t];
    if (t < 64){ sg[t] = g[t]; sb[t] = b[t]; }
    __syncthreads();
    int lp = t >> 6, c = t & 63;
    int p  = blockIdx.x*4 + lp;
    float x0 = x[p*3+0], x1 = x[p*3+1], x2 = x[p*3+2];
    float v = sw[c*3+0]*x0 + sw[c*3+1]*x1 + sw[c*3+2]*x2;
    g_h[p*64+c] = lrelu(v*sg[c] + sb[c]);
}

// ---------------- generic pointwise conv 64 -> COUT with BN+LReLU ----------------
template<int COUT>
__global__ void k_pconv(int sel, const float* __restrict__ w,
                        const float* __restrict__ g, const float* __restrict__ b)
{
    const int PPB = 256/COUT;
    __shared__ float wt[64*COUT];      // transposed: wt[k*COUT+c] = w[c*64+k]
    __shared__ float hs[PPB][64];
    __shared__ float sg[COUT], sb[COUT];
    const float* in  = pconv_in(sel);
    float*       out = pconv_out(sel);
    int t = threadIdx.x;
    for (int i = t; i < 64*COUT; i += 256){ int c = i>>6, k = i&63; wt[k*COUT+c] = w[i]; }
    for (int i = t; i < COUT;    i += 256){ sg[i] = g[i]; sb[i] = b[i]; }
    int lp = t / COUT, c = t % COUT;
    int p  = blockIdx.x*PPB + lp;
    if (c < 64) hs[lp][c] = in[p*64+c];
    __syncthreads();
    float wr[64];
    #pragma unroll
    for (int k = 0; k < 64; k++) wr[k] = wt[k*COUT+c];
    float s = 0.f;
    #pragma unroll
    for (int k = 0; k < 64; k++) s += wr[k]*hs[lp][k];
    out[p*COUT+c] = lrelu(s*sg[c] + sb[c]);
}

// ---------------- squared norms of h (after conv2) and of coords ----------------
__global__ void k_norms(const float* __restrict__ x)
{
    int p = blockIdx.x*256 + threadIdx.x;
    const float* hp = &g_h[p*64];
    float s = 0.f;
    #pragma unroll
    for (int k = 0; k < 64; k++){ float v = hp[k]; s += v*v; }
    g_nh[p] = s;
    float x0 = x[p*3], x1 = x[p*3+1], x2 = x[p*3+2];
    g_nx[p] = x0*x0 + x1*x1 + x2*x2;
}

// ---------------- pair matrix (symmetric): only upper-triangular 64x64 tiles computed;
//                  mirror tile written via smem transpose. pair[n][m]=2*dot-nn[n]-nn[m] ----------------
template<int C>
__global__ void k_pair(int b, const float* __restrict__ x, float* __restrict__ pair)
{
    __shared__ float at[C][68];
    __shared__ float bt[C][68];
    __shared__ float sT[64][68];
    const float* A;
    const float* nn;
    if (C == 64){ A = g_h + (size_t)b*NPTS*64; nn = g_nh + b*NPTS; }
    else        { A = x   + (size_t)b*NPTS*3;  nn = g_nx + b*NPTS; }
    int t  = threadIdx.x;

    // decode triangular tile index -> (bi, bj), bi <= bj
    int u = blockIdx.x;
    int bi = 0, rem = 64;
    while (u >= rem){ u -= rem; rem--; bi++; }
    int bj = bi + u;
    int r0 = bi*64, c0 = bj*64;

    for (int i = t; i < 64*C; i += 256){ int r = i/C, c = i%C; at[c][r] = A[(r0+r)*C + c]; }
    for (int i = t; i < 64*C; i += 256){ int m = i/C, c = i%C; bt[c][m] = A[(c0+m)*C + c]; }
    __syncthreads();
    int tr = (t>>4)<<2, tc = (t&15)<<2;
    float acc[4][4] = {{0.f,0.f,0.f,0.f},{0.f,0.f,0.f,0.f},{0.f,0.f,0.f,0.f},{0.f,0.f,0.f,0.f}};
    #pragma unroll
    for (int c = 0; c < C; c++){
        float4 av = *(const float4*)&at[c][tr];
        float4 bv = *(const float4*)&bt[c][tc];
        acc[0][0] += av.x*bv.x; acc[0][1] += av.x*bv.y; acc[0][2] += av.x*bv.z; acc[0][3] += av.x*bv.w;
        acc[1][0] += av.y*bv.x; acc[1][1] += av.y*bv.y; acc[1][2] += av.y*bv.z; acc[1][3] += av.y*bv.w;
        acc[2][0] += av.z*bv.x; acc[2][1] += av.z*bv.y; acc[2][2] += av.z*bv.z; acc[2][3] += av.z*bv.w;
        acc[3][0] += av.w*bv.x; acc[3][1] += av.w*bv.y; acc[3][2] += av.w*bv.z; acc[3][3] += av.w*bv.w;
    }
    float cn[4];
    #pragma unroll
    for (int j = 0; j < 4; j++) cn[j] = nn[c0+tc+j];
    #pragma unroll
    for (int i = 0; i < 4; i++){
        float rn = nn[r0+tr+i];
        float4 o;
        o.x = 2.f*acc[i][0] - rn - cn[0];
        o.y = 2.f*acc[i][1] - rn - cn[1];
        o.z = 2.f*acc[i][2] - rn - cn[2];
        o.w = 2.f*acc[i][3] - rn - cn[3];
        *(float4*)&pair[(size_t)(r0+tr+i)*NPTS + c0 + tc] = o;
        // stage transposed copy: sT[col][row] = val
        sT[tc+0][tr+i] = o.x;
        sT[tc+1][tr+i] = o.y;
        sT[tc+2][tr+i] = o.z;
        sT[tc+3][tr+i] = o.w;
    }
    if (bi != bj){
        __syncthreads();
        for (int i = t; i < 4096; i += 256){
            int a = i >> 6, bcol = i & 63;
            pair[(size_t)(c0+a)*NPTS + r0 + bcol] = sT[a][bcol];
        }
    }
}

// ---------------- top-20 per row: warp-per-row register selection.
//                  key = (ordered_float << 32) | (4095-idx): max value, ties -> smaller index ----------------
__global__ void k_topk(int b, int which, const float* __restrict__ pair)
{
    __shared__ unsigned long long sh[8][32][21];
    int t    = threadIdx.x;
    int warp = t >> 5, lane = t & 31;
    int row  = blockIdx.x*8 + warp;
    const float* pr = pair + (size_t)row*NPTS;

    unsigned long long lst[KNN];
    #pragma unroll
    for (int i = 0; i < KNN; i++) lst[i] = 0ull;

    #pragma unroll 4
    for (int j = 0; j < 128; j++){
        int i = lane + (j << 5);
        unsigned u = __float_as_uint(__ldg(&pr[i]));
        u = (u & 0x80000000u) ? ~u : (u | 0x80000000u);
        unsigned long long key = ((unsigned long long)u << 32) | (unsigned)(NPTS-1-i);
        if (key > lst[0]){
            bool done = false;
            #pragma unroll
            for (int p = 0; p < KNN-1; p++){
                if (!done){
                    if (key > lst[p+1]) lst[p] = lst[p+1];
                    else { lst[p] = key; done = true; }
                }
            }
            if (!done) lst[KNN-1] = key;
        }
    }

    // spill sorted (ascending) lists and merge
    #pragma unroll
    for (int i = 0; i < KNN; i++) sh[warp][lane][i] = lst[i];
    __syncwarp();

    int* out = (which ? g_idx2 : g_idx1) + ((size_t)b*NPTS + row)*KNN;
    int pos = KNN-1;
    for (int it = 0; it < KNN; it++){
        unsigned long long cand = sh[warp][lane][pos];
        unsigned long long m = cand;
        #pragma unroll
        for (int o = 16; o; o >>= 1){
            unsigned long long other = __shfl_xor_sync(0xffffffffu, m, o);
            if (other > m) m = other;
        }
        if (cand == m) pos--;           // unique keys -> exactly one lane pops
        if (lane == 0) out[it] = NPTS-1 - (int)(m & 0xFFFFFFFFu);
    }
}

// ---------------- dg precompute: a = (Wc-Wd)@h, u = Wd@h ----------------
__global__ void k_dgpre(const float* __restrict__ wdg1)
{
    __shared__ float wct[64*64], wdt[64*64];   // transposed [k][c]
    __shared__ float hs[4][64];
    int t = threadIdx.x;
    for (int i = t; i < 4096; i += 256){
        int c = i>>6, k = i&63;
        float wc = wdg1[c*128 + k], wd = wdg1[c*128 + 64 + k];
        wdt[k*64+c] = wd;
        wct[k*64+c] = wc - wd;
    }
    int lp = t>>6, c = t&63;
    int p  = blockIdx.x*4 + lp;
    hs[lp][c] = g_h[p*64+c];
    __syncthreads();
    float wa[64], wu[64];
    #pragma unroll
    for (int k = 0; k < 64; k++){ wa[k] = wct[k*64+c]; wu[k] = wdt[k*64+c]; }
    float sa = 0.f, su = 0.f;
    #pragma unroll
    for (int k = 0; k < 64; k++){ float h = hs[lp][k]; sa += wa[k]*h; su += wu[k]*h; }
    g_a[p*64+c] = sa;
    g_u[p*64+c] = su;
}

// ---------------- dg edge conv: per edge t1 = lrelu(bn(a_n + u_m)); t2 = dg2 GEMV; max over k ----------------
__global__ void k_dgedge(const float* __restrict__ w2,
                         const float* __restrict__ g1v, const float* __restrict__ b1v,
                         const float* __restrict__ g2v, const float* __restrict__ b2v)
{
    __shared__ float wt[4096];                 // transposed [k][c]
    __shared__ float t1s[4][64];
    __shared__ float sg1[64], sb1[64], sg2[64], sb2[64];
    int t = threadIdx.x;
    for (int i = t; i < 4096; i += 256){ int c = i>>6, k = i&63; wt[k*64+c] = w2[i]; }
    if (t < 64){ sg1[t] = g1v[t]; sb1[t] = b1v[t]; sg2[t] = g2v[t]; sb2[t] = b2v[t]; }
    __syncthreads();
    int lp = t>>6, c = t&63;
    int p    = blockIdx.x*4 + lp;
    int base = (p >> 12) * NPTS;               // batch base
    float wr[64];
    #pragma unroll
    for (int k = 0; k < 64; k++) wr[k] = wt[k*64+c];
    float ac = g_a[p*64+c];
    float G1 = sg1[c], B1 = sb1[c], G2 = sg2[c], B2 = sb2[c];
    float mx = -3.4e38f;
    const int* ip = &g_idx1[p*KNN];
    for (int j = 0; j < KNN; j++){
        int m = ip[j];
        float v = (ac + g_u[(base+m)*64 + c]) * G1 + B1;
        t1s[lp][c] = lrelu(v);
        __syncthreads();
        float s = 0.f;
        #pragma unroll
        for (int k = 0; k < 64; k++) s += wr[k]*t1s[lp][k];
        s = lrelu(s*G2 + B2);
        mx = fmaxf(mx, s);
        __syncthreads();
    }
    g_hdg[p*64+c] = mx;
}

// ---------------- sn branch: gather-max of per-point MLP output ----------------
__global__ void k_snmax()
{
    int t = threadIdx.x;
    int lp = t>>6, c = t&63;
    int p    = blockIdx.x*4 + lp;
    int base = (p >> 12) * NPTS;
    const int* ip = &g_idx2[p*KNN];
    float mx = -3.4e38f;
    for (int j = 0; j < KNN; j++){
        int m = ip[j];
        mx = fmaxf(mx, g_p2[(base+m)*64 + c]);
    }
    g_hsn[p*64+c] = mx;
}

// ---------------- conv5 GEMM: out[b,co,n] = lrelu(bn(w5[co,:] . h4[b,n,:])) ----------------
__global__ void k_conv5(const float* __restrict__ w5, const float* __restrict__ g5,
                        const float* __restrict__ b5, float* __restrict__ out)
{
    __shared__ float wt[64][68];
    __shared__ float ht[64][68];
    int t   = threadIdx.x;
    int co0 = blockIdx.y*64;
    int pt0 = blockIdx.x*64;
    int tr = (t>>4)<<2, tc = (t&15)<<2;
    float acc[4][4] = {{0.f,0.f,0.f,0.f},{0.f,0.f,0.f,0.f},{0.f,0.f,0.f,0.f},{0.f,0.f,0.f,0.f}};
    for (int kc = 0; kc < 2; kc++){
        __syncthreads();
        for (int i = t; i < 4096; i += 256){ int c = i>>6, k = i&63; wt[k][c] = w5[(co0+c)*128 + kc*64 + k]; }
        for (int i = t; i < 4096; i += 256){ int q = i>>6, k = i&63; ht[k][q] = g_h4[(size_t)(pt0+q)*128 + kc*64 + k]; }
        __syncthreads();
        #pragma unroll
        for (int k = 0; k < 64; k++){
            float4 wv = *(const float4*)&wt[k][tr];
            float4 hv = *(const float4*)&ht[k][tc];
            acc[0][0] += wv.x*hv.x; acc[0][1] += wv.x*hv.y; acc[0][2] += wv.x*hv.z; acc[0][3] += wv.x*hv.w;
            acc[1][0] += wv.y*hv.x; acc[1][1] += wv.y*hv.y; acc[1][2] += wv.y*hv.z; acc[1][3] += wv.y*hv.w;
            acc[2][0] += wv.z*hv.x; acc[2][1] += wv.z*hv.y; acc[2][2] += wv.z*hv.z; acc[2][3] += wv.z*hv.w;
            acc[3][0] += wv.w*hv.x; acc[3][1] += wv.w*hv.y; acc[3][2] += wv.w*hv.z; acc[3][3] += wv.w*hv.w;
        }
    }
    int bI = pt0 >> 12;
    int n0 = (pt0 + tc) & (NPTS-1);
    #pragma unroll
    for (int i = 0; i < 4; i++){
        int co = co0 + tr + i;
        float G = g5[co], Bv = b5[co];
        float4 o;
        o.x = lrelu(acc[i][0]*G + Bv);
        o.y = lrelu(acc[i][1]*G + Bv);
        o.z = lrelu(acc[i][2]*G + Bv);
        o.w = lrelu(acc[i][3]*G + Bv);
        *(float4*)&out[((size_t)bI*512 + co)*NPTS + n0] = o;
    }
}

// ---------------- launch ----------------
extern "C" void kernel_launch(void* const* d_in, const int* in_sizes, int n_in,
                              void* d_out, int out_size)
{
    const float* x    = (const float*)d_in[0];
    const float* w1   = (const float*)d_in[1];
    const float* g1   = (const float*)d_in[2];
    const float* b1   = (const float*)d_in[3];
    const float* w2   = (const float*)d_in[4];
    const float* g2   = (const float*)d_in[5];
    const float* b2   = (const float*)d_in[6];
    const float* wdg1 = (const float*)d_in[7];
    const float* gdg1 = (const float*)d_in[8];
    const float* bdg1 = (const float*)d_in[9];
    const float* wdg2 = (const float*)d_in[10];
    const float* gdg2 = (const float*)d_in[11];
    const float* bdg2 = (const float*)d_in[12];
    const float* wsn1 = (const float*)d_in[13];
    const float* gsn1 = (const float*)d_in[14];
    const float* bsn1 = (const float*)d_in[15];
    const float* wsn2 = (const float*)d_in[16];
    const float* gsn2 = (const float*)d_in[17];
    const float* bsn2 = (const float*)d_in[18];
    const float* w3   = (const float*)d_in[19];
    const float* g3   = (const float*)d_in[20];
    const float* b3   = (const float*)d_in[21];
    const float* w4   = (const float*)d_in[22];
    const float* g4   = (const float*)d_in[23];
    const float* b4   = (const float*)d_in[24];
    const float* w5   = (const float*)d_in[25];
    const float* g5   = (const float*)d_in[26];
    const float* b5   = (const float*)d_in[27];

    float* out  = (float*)d_out;
    // d_out (8*512*4096 floats) doubles as the 4096x4096 pair-matrix scratch
    // during the KNN phase; conv5 overwrites it at the very end.
    float* pair = (float*)d_out;

    // conv1 + conv2 (in-place) + norms
    k_conv1   <<<TOTPTS/4, 256>>>(x, w1, g1, b1);
    k_pconv<64><<<TOTPTS/4, 256>>>(0, w2, g2, b2);
    k_norms   <<<TOTPTS/256, 256>>>(x);

    const int NTILE = 64*65/2;   // 2080 upper-triangular tiles
    // KNN on 64-d features -> idx1
    for (int b = 0; b < BB; b++){
        k_pair<64><<<NTILE, 256>>>(b, x, pair);
        k_topk    <<<NPTS/8, 256>>>(b, 0, pair);
    }
    // KNN on 3-d coords -> idx2
    for (int b = 0; b < BB; b++){
        k_pair<3><<<NTILE, 256>>>(b, x, pair);
        k_topk   <<<NPTS/8, 256>>>(b, 1, pair);
    }

    // dg branch
    k_dgpre <<<TOTPTS/4, 256>>>(wdg1);
    k_dgedge<<<TOTPTS/4, 256>>>(wdg2, gdg1, bdg1, gdg2, bdg2);

    // sn branch: per-point MLP then gather-max
    k_pconv<64><<<TOTPTS/4, 256>>>(1, wsn1, gsn1, bsn1);
    k_pconv<64><<<TOTPTS/4, 256>>>(2, wsn2, gsn2, bsn2);
    k_snmax    <<<TOTPTS/4, 256>>>();

    // head
    k_pconv<64> <<<TOTPTS/4, 256>>>(3, w3, g3, b3);
    k_pconv<128><<<TOTPTS/2, 256>>>(4, w4, g4, b4);
    k_conv5     <<<dim3(TOTPTS/64, 512/64), 256>>>(w5, g5, b5, out);
}

// round 6
// speedup vs baseline: 5.0642x; 5.0642x over previous
#include <cuda_runtime.h>

#define BB    8
#define NPTS  4096
#define KNN   20
#define TOTPTS (BB*NPTS)

// ---------------- static device scratch (sanctioned workaround) ----------------
static __device__ float g_h  [TOTPTS*64];   // features after conv1+conv2, (B,N,64)
static __device__ float g_nh [TOTPTS];      // ||h||^2
static __device__ float g_nx [TOTPTS];      // ||x||^2
static __device__ int   g_idx1[TOTPTS*KNN];
static __device__ int   g_idx2[TOTPTS*KNN];
static __device__ float g_a  [TOTPTS*64];   // (Wc-Wd)@h
static __device__ float g_u  [TOTPTS*64];   // Wd@h
static __device__ float g_hdg[TOTPTS*64];   // after dg branch max
static __device__ float g_p2 [TOTPTS*64];   // sn-branch per-point MLP output
static __device__ float g_hsn[TOTPTS*64];   // after sn gather-max (then conv3 in-place)
static __device__ float g_h4 [TOTPTS*128];  // after conv4

__device__ __forceinline__ float lrelu(float v){ return fmaxf(v, 0.01f*v); }

__device__ __forceinline__ const float* pconv_in(int sel){
    switch(sel){ case 0: return g_h; case 1: return g_hdg; case 2: return g_p2;
                 case 3: return g_hsn; default: return g_hsn; }
}
__device__ __forceinline__ float* pconv_out(int sel){
    switch(sel){ case 0: return g_h; case 1: return g_p2; case 2: return g_p2;
                 case 3: return g_hsn; default: return g_h4; }
}

// ---------------- conv1: x(B,N,3) -> g_h (64ch) ----------------
__global__ void k_conv1(const float* __restrict__ x, const float* __restrict__ w,
                        const float* __restrict__ g, const float* __restrict__ b)
{
    __shared__ float sw[192], sg[64], sb[64];
    int t = threadIdx.x;
    if (t < 192) sw[t] = w[t];
    if (t < 64){ sg[t] = g[t]; sb[t] = b[t]; }
    __syncthreads();
    int lp = t >> 6, c = t & 63;
    int p  = blockIdx.x*4 + lp;
    float x0 = x[p*3+0], x1 = x[p*3+1], x2 = x[p*3+2];
    float v = sw[c*3+0]*x0 + sw[c*3+1]*x1 + sw[c*3+2]*x2;
    g_h[p*64+c] = lrelu(v*sg[c] + sb[c]);
}

// ---------------- pointwise conv 64 -> COUT with BN+LReLU; 8 point-groups per block ----------------
template<int COUT>
__global__ void k_pconv(int sel, const float* __restrict__ w,
                        const float* __restrict__ g, const float* __restrict__ b)
{
    const int PPB = 256/COUT;
    const int GRP = 8;
    __shared__ float wt[64*COUT];      // transposed: wt[k*COUT+c] = w[c*64+k]
    __shared__ float hs[PPB][64];
    __shared__ float sg[COUT], sb[COUT];
    const float* in  = pconv_in(sel);
    float*       out = pconv_out(sel);
    int t = threadIdx.x;
    for (int i = t; i < 64*COUT; i += 256){ int c = i>>6, k = i&63; wt[k*COUT+c] = w[i]; }
    for (int i = t; i < COUT;    i += 256){ sg[i] = g[i]; sb[i] = b[i]; }
    __syncthreads();
    int lp = t / COUT, c = t % COUT;
    float wr[64];
    #pragma unroll
    for (int k = 0; k < 64; k++) wr[k] = wt[k*COUT+c];
    float G = sg[c], Bv = sb[c];
    for (int g2 = 0; g2 < GRP; g2++){
        int p = (blockIdx.x*GRP + g2)*PPB + lp;
        __syncthreads();
        if (c < 64) hs[lp][c] = in[p*64+c];
        __syncthreads();
        float s = 0.f;
        #pragma unroll
        for (int k = 0; k < 64; k++) s += wr[k]*hs[lp][k];
        out[p*COUT+c] = lrelu(s*G + Bv);
    }
}

// ---------------- squared norms ----------------
__global__ void k_norms(const float* __restrict__ x)
{
    int p = blockIdx.x*256 + threadIdx.x;
    const float* hp = &g_h[p*64];
    float s = 0.f;
    #pragma unroll
    for (int k = 0; k < 64; k++){ float v = hp[k]; s += v*v; }
    g_nh[p] = s;
    float x0 = x[p*3], x1 = x[p*3+1], x2 = x[p*3+2];
    g_nx[p] = x0*x0 + x1*x1 + x2*x2;
}

// ---------------- pair matrix (symmetric, triangular tiles, exact mirror):
//                  pair[n][m] = 2*dot - (nn[n]+nn[m])  (addition commutes -> mirror bit-exact) ----------------
template<int C>
__global__ void k_pair(int b, const float* __restrict__ x, float* __restrict__ pair)
{
    __shared__ float at[C][68];
    __shared__ float bt[C][68];
    __shared__ float sT[64][68];
    const float* A;
    const float* nn;
    if (C == 64){ A = g_h + (size_t)b*NPTS*64; nn = g_nh + b*NPTS; }
    else        { A = x   + (size_t)b*NPTS*3;  nn = g_nx + b*NPTS; }
    int t  = threadIdx.x;

    int u = blockIdx.x;
    int bi = 0, rem = 64;
    while (u >= rem){ u -= rem; rem--; bi++; }
    int bj = bi + u;
    int r0 = bi*64, c0 = bj*64;

    for (int i = t; i < 64*C; i += 256){ int r = i/C, c = i%C; at[c][r] = A[(r0+r)*C + c]; }
    for (int i = t; i < 64*C; i += 256){ int m = i/C, c = i%C; bt[c][m] = A[(c0+m)*C + c]; }
    __syncthreads();
    int tr = (t>>4)<<2, tc = (t&15)<<2;
    float acc[4][4] = {{0.f,0.f,0.f,0.f},{0.f,0.f,0.f,0.f},{0.f,0.f,0.f,0.f},{0.f,0.f,0.f,0.f}};
    #pragma unroll
    for (int c = 0; c < C; c++){
        float4 av = *(const float4*)&at[c][tr];
        float4 bv = *(const float4*)&bt[c][tc];
        acc[0][0] += av.x*bv.x; acc[0][1] += av.x*bv.y; acc[0][2] += av.x*bv.z; acc[0][3] += av.x*bv.w;
        acc[1][0] += av.y*bv.x; acc[1][1] += av.y*bv.y; acc[1][2] += av.y*bv.z; acc[1][3] += av.y*bv.w;
        acc[2][0] += av.z*bv.x; acc[2][1] += av.z*bv.y; acc[2][2] += av.z*bv.z; acc[2][3] += av.z*bv.w;
        acc[3][0] += av.w*bv.x; acc[3][1] += av.w*bv.y; acc[3][2] += av.w*bv.z; acc[3][3] += av.w*bv.w;
    }
    float cn[4];
    #pragma unroll
    for (int j = 0; j < 4; j++) cn[j] = nn[c0+tc+j];
    #pragma unroll
    for (int i = 0; i < 4; i++){
        float rn = nn[r0+tr+i];
        float4 o;
        o.x = 2.f*acc[i][0] - (rn + cn[0]);
        o.y = 2.f*acc[i][1] - (rn + cn[1]);
        o.z = 2.f*acc[i][2] - (rn + cn[2]);
        o.w = 2.f*acc[i][3] - (rn + cn[3]);
        *(float4*)&pair[(size_t)(r0+tr+i)*NPTS + c0 + tc] = o;
        sT[tc+0][tr+i] = o.x;
        sT[tc+1][tr+i] = o.y;
        sT[tc+2][tr+i] = o.z;
        sT[tc+3][tr+i] = o.w;
    }
    if (bi != bj){
        __syncthreads();
        for (int i = t; i < 4096; i += 256){
            int a = i >> 6, bcol = i & 63;
            pair[(size_t)(c0+a)*NPTS + r0 + bcol] = sT[a][bcol];
        }
    }
}

// ---------------- top-20 per row: block-per-row MSB-first radix select.
//                  order key = (ordered_float(value) << 32) | (4095-idx):
//                  max value first, ties -> smaller index (exact jax.lax.top_k semantics) ----------------
__global__ void k_topk(int b, int which, const float* __restrict__ pair)
{
    __shared__ __align__(16) unsigned int vals[NPTS];
    __shared__ unsigned int hist[256];
    __shared__ unsigned int s_dig, s_rem;
    __shared__ unsigned long long gtlist[32];
    __shared__ unsigned int eqidx[64];
    __shared__ unsigned int s_cntgt, s_cnteq;

    int t = threadIdx.x;
    int lane = t & 31;
    int row = blockIdx.x;
    const float4* pr = (const float4*)(pair + (size_t)row*NPTS);

    // stage row in smem as order-preserving u32
    for (int j = t; j < NPTS/4; j += 256){
        float4 v = __ldg(&pr[j]);
        unsigned u0 = __float_as_uint(v.x); u0 = (u0 & 0x80000000u) ? ~u0 : (u0 | 0x80000000u);
        unsigned u1 = __float_as_uint(v.y); u1 = (u1 & 0x80000000u) ? ~u1 : (u1 | 0x80000000u);
        unsigned u2 = __float_as_uint(v.z); u2 = (u2 & 0x80000000u) ? ~u2 : (u2 | 0x80000000u);
        unsigned u3 = __float_as_uint(v.w); u3 = (u3 & 0x80000000u) ? ~u3 : (u3 | 0x80000000u);
        uint4 o; o.x = u0; o.y = u1; o.z = u2; o.w = u3;
        *(uint4*)&vals[4*j] = o;
    }
    if (t == 0){ s_cntgt = 0; s_cnteq = 0; }

    // 4-digit MSB-first radix select for the exact 20th-largest value
    unsigned prefix = 0;
    unsigned remk   = KNN;
    #pragma unroll
    for (int d = 3; d >= 0; d--){
        __syncthreads();
        hist[t & 255] = 0;               // 256 threads cover all bins
        __syncthreads();
        int sh = d*8;
        unsigned pmask = (d == 3) ? 0u : (0xFFFFFFFFu << (sh+8));
        for (int i = t; i < NPTS; i += 256){
            unsigned v = vals[i];
            if ((v & pmask) == prefix) atomicAdd(&hist[(v >> sh) & 255u], 1u);
        }
        __syncthreads();
        if (t < 32){
            int base = 255 - 8*lane;     // this lane covers bins [base-7 .. base], descending
            unsigned bl[8]; unsigned ssum = 0;
            #pragma unroll
            for (int q = 0; q < 8; q++){ bl[q] = hist[base - q]; ssum += bl[q]; }
            unsigned cum = ssum;         // inclusive scan in descending-bin order
            #pragma unroll
            for (int o = 1; o < 32; o <<= 1){
                unsigned vv = __shfl_up_sync(0xffffffffu, cum, o);
                if (lane >= o) cum += vv;
            }
            unsigned before = cum - ssum;
            if (before < remk && remk <= cum){
                unsigned c2 = before; int dig = base; unsigned r2 = 1; bool fnd = false;
                #pragma unroll
                for (int q = 0; q < 8; q++){
                    if (!fnd && c2 + bl[q] >= remk){ dig = base - q; r2 = remk - c2; fnd = true; }
                    c2 += bl[q];
                }
                s_dig = (unsigned)dig; s_rem = r2;
            }
        }
        __syncthreads();
        prefix |= (s_dig << sh);
        remk = s_rem;
    }
    unsigned thresh = prefix;            // exact 20th-largest ordered value

    // collect candidates: all strictly-greater, plus equal-valued (tie) indices
    for (int i = t; i < NPTS; i += 256){
        unsigned v = vals[i];
        if (v > thresh){
            unsigned p = atomicAdd(&s_cntgt, 1u);
            if (p < 32) gtlist[p] = ((unsigned long long)v << 32) | (unsigned)(NPTS-1-i);
        } else if (v == thresh){
            unsigned p = atomicAdd(&s_cnteq, 1u);
            if (p < 64) eqidx[p] = i;
        }
    }
    __syncthreads();

    // warp 0 emits the 20 results in (value desc, index asc) order
    int* out = (which ? g_idx2 : g_idx1) + ((size_t)b*NPTS + row)*KNN;
    if (t < 32){
        unsigned cgt = s_cntgt;                          // < 20 by construction
        unsigned ceq = s_cnteq < 64u ? s_cnteq : 64u;
        unsigned tot = cgt + ceq;                        // >= 20
        unsigned long long k0 = 0ull, k1 = 0ull;
        if ((unsigned)lane < tot)
            k0 = ((unsigned)lane < cgt) ? gtlist[lane]
               : (((unsigned long long)thresh << 32) | (unsigned)(NPTS-1-eqidx[lane-cgt]));
        if ((unsigned)(lane+32) < tot)
            k1 = ((unsigned long long)thresh << 32) | (unsigned)(NPTS-1-eqidx[lane+32-cgt]);
        for (int it = 0; it < KNN; it++){
            unsigned long long r = (k0 > k1) ? k0 : k1;
            #pragma unroll
            for (int o = 16; o; o >>= 1){
                unsigned long long other = __shfl_xor_sync(0xffffffffu, r, o);
                if (other > r) r = other;
            }
            if (k0 == r) k0 = 0ull;
            else if (k1 == r) k1 = 0ull;
            if (lane == 0) out[it] = (NPTS-1) - (int)(r & 0xFFFFFFFFu);
        }
    }
}

// ---------------- dg precompute: a = (Wc-Wd)@h, u = Wd@h; 8 groups per block ----------------
__global__ void k_dgpre(const float* __restrict__ wdg1)
{
    __shared__ float wct[64*64], wdt[64*64];   // transposed [k][c]
    __shared__ float hs[4][64];
    int t = threadIdx.x;
    for (int i = t; i < 4096; i += 256){
        int c = i>>6, k = i&63;
        float wc = wdg1[c*128 + k], wd = wdg1[c*128 + 64 + k];
        wdt[k*64+c] = wd;
        wct[k*64+c] = wc - wd;
    }
    __syncthreads();
    int lp = t>>6, c = t&63;
    float wa[64], wu[64];
    #pragma unroll
    for (int k = 0; k < 64; k++){ wa[k] = wct[k*64+c]; wu[k] = wdt[k*64+c]; }
    for (int g2 = 0; g2 < 8; g2++){
        int p = (blockIdx.x*8 + g2)*4 + lp;
        __syncthreads();
        hs[lp][c] = g_h[p*64+c];
        __syncthreads();
        float sa = 0.f, su = 0.f;
        #pragma unroll
        for (int k = 0; k < 64; k++){ float h = hs[lp][k]; sa += wa[k]*h; su += wu[k]*h; }
        g_a[p*64+c] = sa;
        g_u[p*64+c] = su;
    }
}

// ---------------- dg edge conv, two-phase (2 barriers total):
//                  phase1: t1[j] = lrelu(bn1(a_n + u_mj)) for all 20 neighbors into smem
//                  phase2: per-channel GEMV over each t1, running max ----------------
__global__ void k_dgedge(const float* __restrict__ w2,
                         const float* __restrict__ g1v, const float* __restrict__ b1v,
                         const float* __restrict__ g2v, const float* __restrict__ b2v)
{
    __shared__ float wt[4096];                 // transposed [k][c]
    __shared__ float t1s[4][KNN][64];
    __shared__ float sg1[64], sb1[64], sg2[64], sb2[64];
    int t = threadIdx.x;
    for (int i = t; i < 4096; i += 256){ int c = i>>6, k = i&63; wt[k*64+c] = w2[i]; }
    if (t < 64){ sg1[t] = g1v[t]; sb1[t] = b1v[t]; sg2[t] = g2v[t]; sb2[t] = b2v[t]; }
    __syncthreads();
    int lp = t>>6, c = t&63;
    int p    = blockIdx.x*4 + lp;
    int base = (p >> 12) * NPTS;
    float ac = g_a[p*64+c];
    float G1 = sg1[c], B1 = sb1[c], G2 = sg2[c], B2 = sb2[c];
    const int* ip = &g_idx1[p*KNN];
    #pragma unroll 5
    for (int j = 0; j < KNN; j++){
        int m = ip[j];
        float v = (ac + g_u[(base+m)*64 + c]) * G1 + B1;
        t1s[lp][j][c] = lrelu(v);
    }
    float wr[64];
    #pragma unroll
    for (int k = 0; k < 64; k++) wr[k] = wt[k*64+c];
    __syncthreads();
    float mx = -3.4e38f;
    for (int j = 0; j < KNN; j++){
        const float4* tp4 = (const float4*)t1s[lp][j];
        float s = 0.f;
        #pragma unroll
        for (int k4 = 0; k4 < 16; k4++){
            float4 hv = tp4[k4];
            s += wr[4*k4+0]*hv.x + wr[4*k4+1]*hv.y + wr[4*k4+2]*hv.z + wr[4*k4+3]*hv.w;
        }
        s = lrelu(s*G2 + B2);
        mx = fmaxf(mx, s);
    }
    g_hdg[p*64+c] = mx;
}

// ---------------- sn branch: gather-max of per-point MLP output ----------------
__global__ void k_snmax()
{
    int t = threadIdx.x;
    int lp = t>>6, c = t&63;
    int p    = blockIdx.x*4 + lp;
    int base = (p >> 12) * NPTS;
    const int* ip = &g_idx2[p*KNN];
    float mx = -3.4e38f;
    for (int j = 0; j < KNN; j++){
        int m = ip[j];
        mx = fmaxf(mx, g_p2[(base+m)*64 + c]);
    }
    g_hsn[p*64+c] = mx;
}

// ---------------- conv5 GEMM: out[b,co,n] = lrelu(bn(w5[co,:] . h4[b,n,:])) ----------------
__global__ void k_conv5(const float* __restrict__ w5, const float* __restrict__ g5,
                        const float* __restrict__ b5, float* __restrict__ out)
{
    __shared__ float wt[64][68];
    __shared__ float ht[64][68];
    int t   = threadIdx.x;
    int co0 = blockIdx.y*64;
    int pt0 = blockIdx.x*64;
    int tr = (t>>4)<<2, tc = (t&15)<<2;
    float acc[4][4] = {{0.f,0.f,0.f,0.f},{0.f,0.f,0.f,0.f},{0.f,0.f,0.f,0.f},{0.f,0.f,0.f,0.f}};
    for (int kc = 0; kc < 2; kc++){
        __syncthreads();
        for (int i = t; i < 4096; i += 256){ int c = i>>6, k = i&63; wt[k][c] = w5[(co0+c)*128 + kc*64 + k]; }
        for (int i = t; i < 4096; i += 256){ int q = i>>6, k = i&63; ht[k][q] = g_h4[(size_t)(pt0+q)*128 + kc*64 + k]; }
        __syncthreads();
        #pragma unroll
        for (int k = 0; k < 64; k++){
            float4 wv = *(const float4*)&wt[k][tr];
            float4 hv = *(const float4*)&ht[k][tc];
            acc[0][0] += wv.x*hv.x; acc[0][1] += wv.x*hv.y; acc[0][2] += wv.x*hv.z; acc[0][3] += wv.x*hv.w;
            acc[1][0] += wv.y*hv.x; acc[1][1] += wv.y*hv.y; acc[1][2] += wv.y*hv.z; acc[1][3] += wv.y*hv.w;
            acc[2][0] += wv.z*hv.x; acc[2][1] += wv.z*hv.y; acc[2][2] += wv.z*hv.z; acc[2][3] += wv.z*hv.w;
            acc[3][0] += wv.w*hv.x; acc[3][1] += wv.w*hv.y; acc[3][2] += wv.w*hv.z; acc[3][3] += wv.w*hv.w;
        }
    }
    int bI = pt0 >> 12;
    int n0 = (pt0 + tc) & (NPTS-1);
    #pragma unroll
    for (int i = 0; i < 4; i++){
        int co = co0 + tr + i;
        float G = g5[co], Bv = b5[co];
        float4 o;
        o.x = lrelu(acc[i][0]*G + Bv);
        o.y = lrelu(acc[i][1]*G + Bv);
        o.z = lrelu(acc[i][2]*G + Bv);
        o.w = lrelu(acc[i][3]*G + Bv);
        *(float4*)&out[((size_t)bI*512 + co)*NPTS + n0] = o;
    }
}

// ---------------- launch ----------------
extern "C" void kernel_launch(void* const* d_in, const int* in_sizes, int n_in,
                              void* d_out, int out_size)
{
    const float* x    = (const float*)d_in[0];
    const float* w1   = (const float*)d_in[1];
    const float* g1   = (const float*)d_in[2];
    const float* b1   = (const float*)d_in[3];
    const float* w2   = (const float*)d_in[4];
    const float* g2   = (const float*)d_in[5];
    const float* b2   = (const float*)d_in[6];
    const float* wdg1 = (const float*)d_in[7];
    const float* gdg1 = (const float*)d_in[8];
    const float* bdg1 = (const float*)d_in[9];
    const float* wdg2 = (const float*)d_in[10];
    const float* gdg2 = (const float*)d_in[11];
    const float* bdg2 = (const float*)d_in[12];
    const float* wsn1 = (const float*)d_in[13];
    const float* gsn1 = (const float*)d_in[14];
    const float* bsn1 = (const float*)d_in[15];
    const float* wsn2 = (const float*)d_in[16];
    const float* gsn2 = (const float*)d_in[17];
    const float* bsn2 = (const float*)d_in[18];
    const float* w3   = (const float*)d_in[19];
    const float* g3   = (const float*)d_in[20];
    const float* b3   = (const float*)d_in[21];
    const float* w4   = (const float*)d_in[22];
    const float* g4   = (const float*)d_in[23];
    const float* b4   = (const float*)d_in[24];
    const float* w5   = (const float*)d_in[25];
    const float* g5   = (const float*)d_in[26];
    const float* b5   = (const float*)d_in[27];

    float* out  = (float*)d_out;
    // d_out (8*512*4096 floats = 64MB) doubles as the 4096x4096 pair-matrix scratch
    float* pair = (float*)d_out;

    // conv1 + conv2 (in-place) + norms
    k_conv1    <<<TOTPTS/4,  256>>>(x, w1, g1, b1);
    k_pconv<64><<<TOTPTS/32, 256>>>(0, w2, g2, b2);
    k_norms    <<<TOTPTS/256,256>>>(x);

    const int NTILE = 64*65/2;   // 2080 upper-triangular tiles
    // KNN on 64-d features -> idx1
    for (int b = 0; b < BB; b++){
        k_pair<64><<<NTILE, 256>>>(b, x, pair);
        k_topk    <<<NPTS,  256>>>(b, 0, pair);
    }
    // KNN on 3-d coords -> idx2
    for (int b = 0; b < BB; b++){
        k_pair<3><<<NTILE, 256>>>(b, x, pair);
        k_topk   <<<NPTS,  256>>>(b, 1, pair);
    }

    // dg branch
    k_dgpre <<<TOTPTS/32, 256>>>(wdg1);
    k_dgedge<<<TOTPTS/4,  256>>>(wdg2, gdg1, bdg1, gdg2, bdg2);

    // sn branch: per-point MLP then gather-max
    k_pconv<64><<<TOTPTS/32, 256>>>(1, wsn1, gsn1, bsn1);
    k_pconv<64><<<TOTPTS/32, 256>>>(2, wsn2, gsn2, bsn2);
    k_snmax    <<<TOTPTS/4,  256>>>();

    // head
    k_pconv<64> <<<TOTPTS/32, 256>>>(3, w3, g3, b3);
    k_pconv<128><<<TOTPTS/16, 256>>>(4, w4, g4, b4);
    k_conv5     <<<dim3(TOTPTS/64, 512/64), 256>>>(w5, g5, b5, out);
}

// round 7
// speedup vs baseline: 5.6483x; 1.1153x over previous
#include <cuda_runtime.h>

#define BB    8
#define NPTS  4096
#define KNN   20
#define TOTPTS (BB*NPTS)

// ---------------- static device scratch (sanctioned workaround) ----------------
static __device__ float g_pair[(size_t)BB*NPTS*NPTS]; // 512MB: all 8 batches' pair matrices
static __device__ float g_h  [TOTPTS*64];   // features after conv1+conv2, (B,N,64)
static __device__ float g_nh [TOTPTS];      // ||h||^2
static __device__ float g_nx [TOTPTS];      // ||x||^2
static __device__ int   g_idx1[TOTPTS*KNN];
static __device__ int   g_idx2[TOTPTS*KNN];
static __device__ float g_a  [TOTPTS*64];   // (Wc-Wd)@h
static __device__ float g_u  [TOTPTS*64];   // Wd@h
static __device__ float g_hdg[TOTPTS*64];   // after dg branch max
static __device__ float g_p2 [TOTPTS*64];   // sn-branch per-point MLP output
static __device__ float g_hsn[TOTPTS*64];   // after sn gather-max (then conv3 in-place)
static __device__ float g_h4 [TOTPTS*128];  // after conv4

__device__ __forceinline__ float lrelu(float v){ return fmaxf(v, 0.01f*v); }

// reference-order epilogue: (2*acc - rn) - cn  (same codegen everywhere)
__device__ __forceinline__ float epi(float acc, float rn, float cn){
    return 2.f*acc - rn - cn;
}

__device__ __forceinline__ const float* pconv_in(int sel){
    switch(sel){ case 0: return g_h; case 1: return g_hdg; case 2: return g_p2;
                 case 3: return g_hsn; default: return g_hsn; }
}
__device__ __forceinline__ float* pconv_out(int sel){
    switch(sel){ case 0: return g_h; case 1: return g_p2; case 2: return g_p2;
                 case 3: return g_hsn; default: return g_h4; }
}

// ---------------- conv1: x(B,N,3) -> g_h (64ch) ----------------
__global__ void k_conv1(const float* __restrict__ x, const float* __restrict__ w,
                        const float* __restrict__ g, const float* __restrict__ b)
{
    __shared__ float sw[192], sg[64], sb[64];
    int t = threadIdx.x;
    if (t < 192) sw[t] = w[t];
    if (t < 64){ sg[t] = g[t]; sb[t] = b[t]; }
    __syncthreads();
    int lp = t >> 6, c = t & 63;
    int p  = blockIdx.x*4 + lp;
    float x0 = x[p*3+0], x1 = x[p*3+1], x2 = x[p*3+2];
    float v = sw[c*3+0]*x0 + sw[c*3+1]*x1 + sw[c*3+2]*x2;
    g_h[p*64+c] = lrelu(v*sg[c] + sb[c]);
}

// ---------------- pointwise conv 64 -> COUT with BN+LReLU; 8 point-groups per block ----------------
template<int COUT>
__global__ void k_pconv(int sel, const float* __restrict__ w,
                        const float* __restrict__ g, const float* __restrict__ b)
{
    const int PPB = 256/COUT;
    const int GRP = 8;
    __shared__ float wt[64*COUT];
    __shared__ float hs[PPB][64];
    __shared__ float sg[COUT], sb[COUT];
    const float* in  = pconv_in(sel);
    float*       out = pconv_out(sel);
    int t = threadIdx.x;
    for (int i = t; i < 64*COUT; i += 256){ int c = i>>6, k = i&63; wt[k*COUT+c] = w[i]; }
    for (int i = t; i < COUT;    i += 256){ sg[i] = g[i]; sb[i] = b[i]; }
    __syncthreads();
    int lp = t / COUT, c = t % COUT;
    float wr[64];
    #pragma unroll
    for (int k = 0; k < 64; k++) wr[k] = wt[k*COUT+c];
    float G = sg[c], Bv = sb[c];
    for (int g2 = 0; g2 < GRP; g2++){
        int p = (blockIdx.x*GRP + g2)*PPB + lp;
        __syncthreads();
        if (c < 64) hs[lp][c] = in[p*64+c];
        __syncthreads();
        float s = 0.f;
        #pragma unroll
        for (int k = 0; k < 64; k++) s += wr[k]*hs[lp][k];
        out[p*COUT+c] = lrelu(s*G + Bv);
    }
}

// ---------------- squared norms ----------------
__global__ void k_norms(const float* __restrict__ x)
{
    int p = blockIdx.x*256 + threadIdx.x;
    const float* hp = &g_h[p*64];
    float s = 0.f;
    #pragma unroll
    for (int k = 0; k < 64; k++){ float v = hp[k]; s += v*v; }
    g_nh[p] = s;
    float x0 = x[p*3], x1 = x[p*3+1], x2 = x[p*3+2];
    float sx = 0.f;
    sx = fmaf(x0,x0,sx); sx = fmaf(x1,x1,sx); sx = fmaf(x2,x2,sx);
    g_nx[p] = sx;
}

// ---------------- feature pair matrix, all batches (blockIdx.y = batch):
//                  upper-triangular tiles computed; mirror staged (raw dot) then
//                  written with reference-order epilogue -> bit-exact both halves ----------------
__global__ void k_pair(void)
{
    __shared__ float at[64][68];
    __shared__ float bt[64][68];
    int b = blockIdx.y;
    const float* A  = g_h + (size_t)b*NPTS*64;
    const float* nn = g_nh + b*NPTS;
    float* pair = g_pair + (size_t)b*NPTS*NPTS;
    int t  = threadIdx.x;

    int u = blockIdx.x;
    int bi = 0, rem = 64;
    while (u >= rem){ u -= rem; rem--; bi++; }
    int bj = bi + u;
    int r0 = bi*64, c0 = bj*64;

    for (int i = t; i < 4096; i += 256){ int r = i>>6, c = i&63; at[c][r] = A[(size_t)(r0+r)*64 + c]; }
    for (int i = t; i < 4096; i += 256){ int m = i>>6, c = i&63; bt[c][m] = A[(size_t)(c0+m)*64 + c]; }
    __syncthreads();
    int tr = (t>>4)<<2, tc = (t&15)<<2;
    float acc[4][4] = {{0.f,0.f,0.f,0.f},{0.f,0.f,0.f,0.f},{0.f,0.f,0.f,0.f},{0.f,0.f,0.f,0.f}};
    #pragma unroll
    for (int c = 0; c < 64; c++){
        float4 av = *(const float4*)&at[c][tr];
        float4 bv = *(const float4*)&bt[c][tc];
        acc[0][0] += av.x*bv.x; acc[0][1] += av.x*bv.y; acc[0][2] += av.x*bv.z; acc[0][3] += av.x*bv.w;
        acc[1][0] += av.y*bv.x; acc[1][1] += av.y*bv.y; acc[1][2] += av.y*bv.z; acc[1][3] += av.y*bv.w;
        acc[2][0] += av.z*bv.x; acc[2][1] += av.z*bv.y; acc[2][2] += av.z*bv.z; acc[2][3] += av.z*bv.w;
        acc[3][0] += av.w*bv.x; acc[3][1] += av.w*bv.y; acc[3][2] += av.w*bv.z; acc[3][3] += av.w*bv.w;
    }
    float cn[4];
    #pragma unroll
    for (int j = 0; j < 4; j++) cn[j] = nn[c0+tc+j];
    // direct output (reference epilogue order)
    #pragma unroll
    for (int i = 0; i < 4; i++){
        float rn = nn[r0+tr+i];
        float4 o;
        o.x = epi(acc[i][0], rn, cn[0]);
        o.y = epi(acc[i][1], rn, cn[1]);
        o.z = epi(acc[i][2], rn, cn[2]);
        o.w = epi(acc[i][3], rn, cn[3]);
        *(float4*)&pair[(size_t)(r0+tr+i)*NPTS + c0 + tc] = o;
    }
    if (bi != bj){
        // stage RAW dot products transposed into at (dead now), then mirror with
        // the mirror element's own (rn', cn') in reference order
        float (*sT)[68] = at;
        __syncthreads();
        #pragma unroll
        for (int i = 0; i < 4; i++){
            sT[tc+0][tr+i] = acc[i][0];
            sT[tc+1][tr+i] = acc[i][1];
            sT[tc+2][tr+i] = acc[i][2];
            sT[tc+3][tr+i] = acc[i][3];
        }
        __syncthreads();
        for (int i = t; i < 4096; i += 256){
            int a = i >> 6, bcol = i & 63;
            pair[(size_t)(c0+a)*NPTS + r0 + bcol] = epi(sT[a][bcol], nn[c0+a], nn[r0+bcol]);
        }
    }
}

// ---------------- shared radix-select core: exact top-20 of vals[0..4095]
//                  (ordered-u32; key = (val<<32)|(4095-idx): value desc, index asc) ----------------
__device__ __forceinline__ void top20_select(
    unsigned* vals, unsigned* hist, unsigned long long* gtlist, unsigned* eqidx,
    unsigned* sc /* [0]=dig [1]=rem [2]=cntgt [3]=cnteq */, int* out)
{
    int t = threadIdx.x;
    int lane = t & 31;
    if (t == 0){ sc[2] = 0; sc[3] = 0; }

    unsigned prefix = 0;
    unsigned remk   = KNN;
    #pragma unroll
    for (int d = 3; d >= 0; d--){
        __syncthreads();
        hist[t & 255] = 0;
        __syncthreads();
        int sh = d*8;
        unsigned pmask = (d == 3) ? 0u : (0xFFFFFFFFu << (sh+8));
        for (int i = t; i < NPTS; i += 256){
            unsigned v = vals[i];
            if ((v & pmask) == prefix) atomicAdd(&hist[(v >> sh) & 255u], 1u);
        }
        __syncthreads();
        if (t < 32){
            int base = 255 - 8*lane;
            unsigned bl[8]; unsigned ssum = 0;
            #pragma unroll
            for (int q = 0; q < 8; q++){ bl[q] = hist[base - q]; ssum += bl[q]; }
            unsigned cum = ssum;
            #pragma unroll
            for (int o = 1; o < 32; o <<= 1){
                unsigned vv = __shfl_up_sync(0xffffffffu, cum, o);
                if (lane >= o) cum += vv;
            }
            unsigned before = cum - ssum;
            if (before < remk && remk <= cum){
                unsigned c2 = before; int dig = base; unsigned r2 = 1; bool fnd = false;
                #pragma unroll
                for (int q = 0; q < 8; q++){
                    if (!fnd && c2 + bl[q] >= remk){ dig = base - q; r2 = remk - c2; fnd = true; }
                    c2 += bl[q];
                }
                sc[0] = (unsigned)dig; sc[1] = r2;
            }
        }
        __syncthreads();
        prefix |= (sc[0] << sh);
        remk = sc[1];
    }
    unsigned thresh = prefix;

    for (int i = t; i < NPTS; i += 256){
        unsigned v = vals[i];
        if (v > thresh){
            unsigned p = atomicAdd(&sc[2], 1u);
            if (p < 32) gtlist[p] = ((unsigned long long)v << 32) | (unsigned)(NPTS-1-i);
        } else if (v == thresh){
            unsigned p = atomicAdd(&sc[3], 1u);
            if (p < 64) eqidx[p] = i;
        }
    }
    __syncthreads();

    if (t < 32){
        unsigned cgt = sc[2];
        unsigned ceq = sc[3] < 64u ? sc[3] : 64u;
        unsigned tot = cgt + ceq;
        unsigned long long k0 = 0ull, k1 = 0ull;
        if ((unsigned)lane < tot)
            k0 = ((unsigned)lane < cgt) ? gtlist[lane]
               : (((unsigned long long)thresh << 32) | (unsigned)(NPTS-1-eqidx[lane-cgt]));
        if ((unsigned)(lane+32) < tot)
            k1 = ((unsigned long long)thresh << 32) | (unsigned)(NPTS-1-eqidx[lane+32-cgt]);
        for (int it = 0; it < KNN; it++){
            unsigned long long r = (k0 > k1) ? k0 : k1;
            #pragma unroll
            for (int o = 16; o; o >>= 1){
                unsigned long long other = __shfl_xor_sync(0xffffffffu, r, o);
                if (other > r) r = other;
            }
            if (k0 == r) k0 = 0ull;
            else if (k1 == r) k1 = 0ull;
            if (lane == 0) out[it] = (NPTS-1) - (int)(r & 0xFFFFFFFFu);
        }
    }
}

__device__ __forceinline__ unsigned f2ord(float f){
    unsigned u = __float_as_uint(f);
    return (u & 0x80000000u) ? ~u : (u | 0x80000000u);
}

// ---------------- feature top-k: block per (row, batch) over g_pair ----------------
__global__ void k_topk(void)
{
    __shared__ __align__(16) unsigned int vals[NPTS];
    __shared__ unsigned int hist[256];
    __shared__ unsigned long long gtlist[32];
    __shared__ unsigned int eqidx[64];
    __shared__ unsigned int sc[4];

    int t = threadIdx.x;
    int row = blockIdx.x, b = blockIdx.y;
    const float4* pr = (const float4*)(g_pair + (size_t)b*NPTS*NPTS + (size_t)row*NPTS);
    for (int j = t; j < NPTS/4; j += 256){
        float4 v = __ldg(&pr[j]);
        uint4 o; o.x = f2ord(v.x); o.y = f2ord(v.y); o.z = f2ord(v.z); o.w = f2ord(v.w);
        *(uint4*)&vals[4*j] = o;
    }
    int* out = g_idx1 + ((size_t)b*NPTS + row)*KNN;
    top20_select(vals, hist, gtlist, eqidx, sc, out);
}

// ---------------- coordinate KNN, fused distance + select: block per (row, batch) ----------------
__global__ void k_knn3(const float* __restrict__ x)
{
    __shared__ __align__(16) unsigned int vals[NPTS];
    __shared__ unsigned int hist[256];
    __shared__ unsigned long long gtlist[32];
    __shared__ unsigned int eqidx[64];
    __shared__ unsigned int sc[4];

    int t = threadIdx.x;
    int row = blockIdx.x, b = blockIdx.y;
    const float* xb = x + (size_t)b*NPTS*3;
    const float* nn = g_nx + b*NPTS;
    float xr0 = xb[row*3+0], xr1 = xb[row*3+1], xr2 = xb[row*3+2];
    float rn = nn[row];
    for (int i = t; i < NPTS; i += 256){
        float m0 = __ldg(&xb[i*3+0]), m1 = __ldg(&xb[i*3+1]), m2 = __ldg(&xb[i*3+2]);
        float s = 0.f;
        s = fmaf(xr0, m0, s); s = fmaf(xr1, m1, s); s = fmaf(xr2, m2, s);
        vals[i] = f2ord(epi(s, rn, nn[i]));
    }
    int* out = g_idx2 + ((size_t)b*NPTS + row)*KNN;
    top20_select(vals, hist, gtlist, eqidx, sc, out);
}

// ---------------- dg precompute: a = (Wc-Wd)@h, u = Wd@h; 8 groups per block ----------------
__global__ void k_dgpre(const float* __restrict__ wdg1)
{
    __shared__ float wct[64*64], wdt[64*64];
    __shared__ float hs[4][64];
    int t = threadIdx.x;
    for (int i = t; i < 4096; i += 256){
        int c = i>>6, k = i&63;
        float wc = wdg1[c*128 + k], wd = wdg1[c*128 + 64 + k];
        wdt[k*64+c] = wd;
        wct[k*64+c] = wc - wd;
    }
    __syncthreads();
    int lp = t>>6, c = t&63;
    float wa[64], wu[64];
    #pragma unroll
    for (int k = 0; k < 64; k++){ wa[k] = wct[k*64+c]; wu[k] = wdt[k*64+c]; }
    for (int g2 = 0; g2 < 8; g2++){
        int p = (blockIdx.x*8 + g2)*4 + lp;
        __syncthreads();
        hs[lp][c] = g_h[p*64+c];
        __syncthreads();
        float sa = 0.f, su = 0.f;
        #pragma unroll
        for (int k = 0; k < 64; k++){ float h = hs[lp][k]; sa += wa[k]*h; su += wu[k]*h; }
        g_a[p*64+c] = sa;
        g_u[p*64+c] = su;
    }
}

// ---------------- dg edge conv, two-phase ----------------
__global__ void k_dgedge(const float* __restrict__ w2,
                         const float* __restrict__ g1v, const float* __restrict__ b1v,
                         const float* __restrict__ g2v, const float* __restrict__ b2v)
{
    __shared__ float wt[4096];
    __shared__ float t1s[4][KNN][64];
    __shared__ float sg1[64], sb1[64], sg2[64], sb2[64];
    int t = threadIdx.x;
    for (int i = t; i < 4096; i += 256){ int c = i>>6, k = i&63; wt[k*64+c] = w2[i]; }
    if (t < 64){ sg1[t] = g1v[t]; sb1[t] = b1v[t]; sg2[t] = g2v[t]; sb2[t] = b2v[t]; }
    __syncthreads();
    int lp = t>>6, c = t&63;
    int p    = blockIdx.x*4 + lp;
    int base = (p >> 12) * NPTS;
    float ac = g_a[p*64+c];
    float G1 = sg1[c], B1 = sb1[c], G2 = sg2[c], B2 = sb2[c];
    const int* ip = &g_idx1[p*KNN];
    #pragma unroll 5
    for (int j = 0; j < KNN; j++){
        int m = ip[j];
        float v = (ac + g_u[(base+m)*64 + c]) * G1 + B1;
        t1s[lp][j][c] = lrelu(v);
    }
    float wr[64];
    #pragma unroll
    for (int k = 0; k < 64; k++) wr[k] = wt[k*64+c];
    __syncthreads();
    float mx = -3.4e38f;
    for (int j = 0; j < KNN; j++){
        const float4* tp4 = (const float4*)t1s[lp][j];
        float s = 0.f;
        #pragma unroll
        for (int k4 = 0; k4 < 16; k4++){
            float4 hv = tp4[k4];
            s += wr[4*k4+0]*hv.x + wr[4*k4+1]*hv.y + wr[4*k4+2]*hv.z + wr[4*k4+3]*hv.w;
        }
        s = lrelu(s*G2 + B2);
        mx = fmaxf(mx, s);
    }
    g_hdg[p*64+c] = mx;
}

// ---------------- sn branch: gather-max of per-point MLP output ----------------
__global__ void k_snmax()
{
    int t = threadIdx.x;
    int lp = t>>6, c = t&63;
    int p    = blockIdx.x*4 + lp;
    int base = (p >> 12) * NPTS;
    const int* ip = &g_idx2[p*KNN];
    float mx = -3.4e38f;
    for (int j = 0; j < KNN; j++){
        int m = ip[j];
        mx = fmaxf(mx, g_p2[(base+m)*64 + c]);
    }
    g_hsn[p*64+c] = mx;
}

// ---------------- conv5 GEMM ----------------
__global__ void k_conv5(const float* __restrict__ w5, const float* __restrict__ g5,
                        const float* __restrict__ b5, float* __restrict__ out)
{
    __shared__ float wt[64][68];
    __shared__ float ht[64][68];
    int t   = threadIdx.x;
    int co0 = blockIdx.y*64;
    int pt0 = blockIdx.x*64;
    int tr = (t>>4)<<2, tc = (t&15)<<2;
    float acc[4][4] = {{0.f,0.f,0.f,0.f},{0.f,0.f,0.f,0.f},{0.f,0.f,0.f,0.f},{0.f,0.f,0.f,0.f}};
    for (int kc = 0; kc < 2; kc++){
        __syncthreads();
        for (int i = t; i < 4096; i += 256){ int c = i>>6, k = i&63; wt[k][c] = w5[(co0+c)*128 + kc*64 + k]; }
        for (int i = t; i < 4096; i += 256){ int q = i>>6, k = i&63; ht[k][q] = g_h4[(size_t)(pt0+q)*128 + kc*64 + k]; }
        __syncthreads();
        #pragma unroll
        for (int k = 0; k < 64; k++){
            float4 wv = *(const float4*)&wt[k][tr];
            float4 hv = *(const float4*)&ht[k][tc];
            acc[0][0] += wv.x*hv.x; acc[0][1] += wv.x*hv.y; acc[0][2] += wv.x*hv.z; acc[0][3] += wv.x*hv.w;
            acc[1][0] += wv.y*hv.x; acc[1][1] += wv.y*hv.y; acc[1][2] += wv.y*hv.z; acc[1][3] += wv.y*hv.w;
            acc[2][0] += wv.z*hv.x; acc[2][1] += wv.z*hv.y; acc[2][2] += wv.z*hv.z; acc[2][3] += wv.z*hv.w;
            acc[3][0] += wv.w*hv.x; acc[3][1] += wv.w*hv.y; acc[3][2] += wv.w*hv.z; acc[3][3] += wv.w*hv.w;
        }
    }
    int bI = pt0 >> 12;
    int n0 = (pt0 + tc) & (NPTS-1);
    #pragma unroll
    for (int i = 0; i < 4; i++){
        int co = co0 + tr + i;
        float G = g5[co], Bv = b5[co];
        float4 o;
        o.x = lrelu(acc[i][0]*G + Bv);
        o.y = lrelu(acc[i][1]*G + Bv);
        o.z = lrelu(acc[i][2]*G + Bv);
        o.w = lrelu(acc[i][3]*G + Bv);
        *(float4*)&out[((size_t)bI*512 + co)*NPTS + n0] = o;
    }
}

// ---------------- launch ----------------
extern "C" void kernel_launch(void* const* d_in, const int* in_sizes, int n_in,
                              void* d_out, int out_size)
{
    const float* x    = (const float*)d_in[0];
    const float* w1   = (const float*)d_in[1];
    const float* g1   = (const float*)d_in[2];
    const float* b1   = (const float*)d_in[3];
    const float* w2   = (const float*)d_in[4];
    const float* g2   = (const float*)d_in[5];
    const float* b2   = (const float*)d_in[6];
    const float* wdg1 = (const float*)d_in[7];
    const float* gdg1 = (const float*)d_in[8];
    const float* bdg1 = (const float*)d_in[9];
    const float* wdg2 = (const float*)d_in[10];
    const float* gdg2 = (const float*)d_in[11];
    const float* bdg2 = (const float*)d_in[12];
    const float* wsn1 = (const float*)d_in[13];
    const float* gsn1 = (const float*)d_in[14];
    const float* bsn1 = (const float*)d_in[15];
    const float* wsn2 = (const float*)d_in[16];
    const float* gsn2 = (const float*)d_in[17];
    const float* bsn2 = (const float*)d_in[18];
    const float* w3   = (const float*)d_in[19];
    const float* g3   = (const float*)d_in[20];
    const float* b3   = (const float*)d_in[21];
    const float* w4   = (const float*)d_in[22];
    const float* g4   = (const float*)d_in[23];
    const float* b4   = (const float*)d_in[24];
    const float* w5   = (const float*)d_in[25];
    const float* g5   = (const float*)d_in[26];
    const float* b5   = (const float*)d_in[27];

    float* out  = (float*)d_out;

    // conv1 + conv2 (in-place) + norms
    k_conv1    <<<TOTPTS/4,  256>>>(x, w1, g1, b1);
    k_pconv<64><<<TOTPTS/32, 256>>>(0, w2, g2, b2);
    k_norms    <<<TOTPTS/256,256>>>(x);

    const int NTILE = 64*65/2;   // 2080 upper-triangular tiles
    // feature KNN (all batches, single launches)
    k_pair<<<dim3(NTILE, BB), 256>>>();
    k_topk<<<dim3(NPTS,  BB), 256>>>();
    // coordinate KNN (fused distance + select)
    k_knn3<<<dim3(NPTS,  BB), 256>>>(x);

    // dg branch
    k_dgpre <<<TOTPTS/32, 256>>>(wdg1);
    k_dgedge<<<TOTPTS/4,  256>>>(wdg2, gdg1, bdg1, gdg2, bdg2);

    // sn branch: per-point MLP then gather-max
    k_pconv<64><<<TOTPTS/32, 256>>>(1, wsn1, gsn1, bsn1);
    k_pconv<64><<<TOTPTS/32, 256>>>(2, wsn2, gsn2, bsn2);
    k_snmax    <<<TOTPTS/4,  256>>>();

    // head
    k_pconv<64> <<<TOTPTS/32, 256>>>(3, w3, g3, b3);
    k_pconv<128><<<TOTPTS/16, 256>>>(4, w4, g4, b4);
    k_conv5     <<<dim3(TOTPTS/64, 512/64), 256>>>(w5, g5, b5, out);
}

// round 8
// speedup vs baseline: 5.7380x; 1.0159x over previous
#include <cuda_runtime.h>

#define BB    8
#define NPTS  4096
#define KNN   20
#define TOTPTS (BB*NPTS)
#define BUFSZ 1024

// ---------------- static device scratch (sanctioned workaround) ----------------
static __device__ float g_pair[(size_t)BB*NPTS*NPTS]; // 512MB: all 8 batches' pair matrices
static __device__ float g_h  [TOTPTS*64];   // features after conv1+conv2, (B,N,64)
static __device__ float g_nh [TOTPTS];      // ||h||^2
static __device__ float g_nx [TOTPTS];      // ||x||^2
static __device__ int   g_idx1[TOTPTS*KNN];
static __device__ int   g_idx2[TOTPTS*KNN];
static __device__ float g_a  [TOTPTS*64];   // (Wc-Wd)@h
static __device__ float g_u  [TOTPTS*64];   // Wd@h
static __device__ float g_hdg[TOTPTS*64];   // after dg branch max
static __device__ float g_p2 [TOTPTS*64];   // sn-branch per-point MLP output
static __device__ float g_hsn[TOTPTS*64];   // after sn gather-max (then conv3 in-place)
static __device__ float g_h4 [TOTPTS*128];  // after conv4

__device__ __forceinline__ float lrelu(float v){ return fmaxf(v, 0.01f*v); }

// reference-order epilogue (identical codegen at every use site)
__device__ __forceinline__ float epi(float acc, float rn, float cn){
    return 2.f*acc - rn - cn;
}

__device__ __forceinline__ unsigned f2ord(float f){
    unsigned u = __float_as_uint(f);
    return (u & 0x80000000u) ? ~u : (u | 0x80000000u);
}

__device__ __forceinline__ const float* pconv_in(int sel){
    switch(sel){ case 0: return g_h; case 1: return g_hdg; case 2: return g_p2;
                 case 3: return g_hsn; default: return g_hsn; }
}
__device__ __forceinline__ float* pconv_out(int sel){
    switch(sel){ case 0: return g_h; case 1: return g_p2; case 2: return g_p2;
                 case 3: return g_hsn; default: return g_h4; }
}

// ---------------- conv1: x(B,N,3) -> g_h (64ch) ----------------
__global__ void k_conv1(const float* __restrict__ x, const float* __restrict__ w,
                        const float* __restrict__ g, const float* __restrict__ b)
{
    __shared__ float sw[192], sg[64], sb[64];
    int t = threadIdx.x;
    if (t < 192) sw[t] = w[t];
    if (t < 64){ sg[t] = g[t]; sb[t] = b[t]; }
    __syncthreads();
    int lp = t >> 6, c = t & 63;
    int p  = blockIdx.x*4 + lp;
    float x0 = x[p*3+0], x1 = x[p*3+1], x2 = x[p*3+2];
    float v = sw[c*3+0]*x0 + sw[c*3+1]*x1 + sw[c*3+2]*x2;
    g_h[p*64+c] = lrelu(v*sg[c] + sb[c]);
}

// ---------------- pointwise conv 64 -> COUT with BN+LReLU; 8 point-groups per block ----------------
template<int COUT>
__global__ void k_pconv(int sel, const float* __restrict__ w,
                        const float* __restrict__ g, const float* __restrict__ b)
{
    const int PPB = 256/COUT;
    const int GRP = 8;
    __shared__ float wt[64*COUT];
    __shared__ float hs[PPB][64];
    __shared__ float sg[COUT], sb[COUT];
    const float* in  = pconv_in(sel);
    float*       out = pconv_out(sel);
    int t = threadIdx.x;
    for (int i = t; i < 64*COUT; i += 256){ int c = i>>6, k = i&63; wt[k*COUT+c] = w[i]; }
    for (int i = t; i < COUT;    i += 256){ sg[i] = g[i]; sb[i] = b[i]; }
    __syncthreads();
    int lp = t / COUT, c = t % COUT;
    float wr[64];
    #pragma unroll
    for (int k = 0; k < 64; k++) wr[k] = wt[k*COUT+c];
    float G = sg[c], Bv = sb[c];
    for (int g2 = 0; g2 < GRP; g2++){
        int p = (blockIdx.x*GRP + g2)*PPB + lp;
        __syncthreads();
        if (c < 64) hs[lp][c] = in[p*64+c];
        __syncthreads();
        float s = 0.f;
        #pragma unroll
        for (int k = 0; k < 64; k++) s += wr[k]*hs[lp][k];
        out[p*COUT+c] = lrelu(s*G + Bv);
    }
}

// ---------------- squared norms ----------------
__global__ void k_norms(const float* __restrict__ x)
{
    int p = blockIdx.x*256 + threadIdx.x;
    const float* hp = &g_h[p*64];
    float s = 0.f;
    #pragma unroll
    for (int k = 0; k < 64; k++){ float v = hp[k]; s += v*v; }
    g_nh[p] = s;
    float x0 = x[p*3], x1 = x[p*3+1], x2 = x[p*3+2];
    float sx = 0.f;
    sx = fmaf(x0,x0,sx); sx = fmaf(x1,x1,sx); sx = fmaf(x2,x2,sx);
    g_nx[p] = sx;
}

// ---------------- feature pair matrix: 128x128 tiles, 8x8 per thread,
//                  triangular over 32x32 tile grid; mirror via raw-dot smem staging ----------------
__global__ void __launch_bounds__(256, 2) k_pair(void)
{
    __shared__ float sBuf[2*32*132];
    float (*sA)[132] = (float(*)[132])sBuf;
    float (*sB)[132] = (float(*)[132])(sBuf + 32*132);
    float (*sM)[132] = (float(*)[132])sBuf;   // mirror staging alias (64 rows x 128 cols)

    int b = blockIdx.y;
    const float* A  = g_h + (size_t)b*NPTS*64;
    const float* nn = g_nh + b*NPTS;
    float* pair = g_pair + (size_t)b*NPTS*NPTS;
    int t = threadIdx.x;

    // triangular decode over 32x32 tiles of 128
    int u = blockIdx.x;
    int bi = 0, rem = 32;
    while (u >= rem){ u -= rem; rem--; bi++; }
    int bj = bi + u;
    int r0 = bi*128, c0 = bj*128;

    int ty = t >> 4, tx = t & 15;
    float acc[8][8];
    #pragma unroll
    for (int i = 0; i < 8; i++)
        #pragma unroll
        for (int j = 0; j < 8; j++) acc[i][j] = 0.f;

    for (int kc = 0; kc < 2; kc++){
        __syncthreads();
        for (int i = t; i < 128*32; i += 256){
            int r = i >> 5, c = i & 31;
            sA[c][r] = A[(size_t)(r0+r)*64 + kc*32 + c];
        }
        for (int i = t; i < 128*32; i += 256){
            int r = i >> 5, c = i & 31;
            sB[c][r] = A[(size_t)(c0+r)*64 + kc*32 + c];
        }
        __syncthreads();
        #pragma unroll
        for (int c = 0; c < 32; c++){
            float4 a0 = *(const float4*)&sA[c][ty*4];
            float4 a1 = *(const float4*)&sA[c][ty*4+64];
            float4 b0 = *(const float4*)&sB[c][tx*4];
            float4 b1 = *(const float4*)&sB[c][tx*4+64];
            float av[8] = {a0.x,a0.y,a0.z,a0.w,a1.x,a1.y,a1.z,a1.w};
            float bv[8] = {b0.x,b0.y,b0.z,b0.w,b1.x,b1.y,b1.z,b1.w};
            #pragma unroll
            for (int i = 0; i < 8; i++)
                #pragma unroll
                for (int j = 0; j < 8; j++) acc[i][j] += av[i]*bv[j];
        }
    }

    // direct output (reference epilogue order), rows split lo/hi 64
    float cnv[8];
    #pragma unroll
    for (int j = 0; j < 8; j++) cnv[j] = nn[c0 + ((j>>2)<<6) + tx*4 + (j&3)];
    #pragma unroll
    for (int i = 0; i < 8; i++){
        int gr = r0 + ((i>>2)<<6) + ty*4 + (i&3);
        float rn = nn[gr];
        float4 o0, o1;
        o0.x = epi(acc[i][0], rn, cnv[0]);
        o0.y = epi(acc[i][1], rn, cnv[1]);
        o0.z = epi(acc[i][2], rn, cnv[2]);
        o0.w = epi(acc[i][3], rn, cnv[3]);
        o1.x = epi(acc[i][4], rn, cnv[4]);
        o1.y = epi(acc[i][5], rn, cnv[5]);
        o1.z = epi(acc[i][6], rn, cnv[6]);
        o1.w = epi(acc[i][7], rn, cnv[7]);
        *(float4*)&pair[(size_t)gr*NPTS + c0 + tx*4]      = o0;
        *(float4*)&pair[(size_t)gr*NPTS + c0 + 64 + tx*4] = o1;
    }

    if (bi != bj){
        // mirror in two 64-col chunks via raw-dot staging (bit-exact vs direct)
        #pragma unroll
        for (int h = 0; h < 2; h++){
            __syncthreads();
            #pragma unroll
            for (int i = 0; i < 8; i++){
                int lr = ((i>>2)<<6) + ty*4 + (i&3);
                #pragma unroll
                for (int q = 0; q < 4; q++)
                    sM[tx*4+q][lr] = acc[i][4*h+q];
            }
            __syncthreads();
            for (int i = t; i < 64*128; i += 256){
                int a = i >> 7, col = i & 127;
                int gr = c0 + h*64 + a;
                pair[(size_t)gr*NPTS + r0 + col] = epi(sM[a][col], nn[gr], nn[r0+col]);
            }
        }
    }
}

// ---------------- radix digit finder (descending bins), warp 0 ----------------
__device__ __forceinline__ void find_digit(unsigned* hist, unsigned remk, unsigned* sc)
{
    int t = threadIdx.x, lane = t & 31;
    if (t < 32){
        int base = 255 - 8*lane;
        unsigned bl[8]; unsigned ssum = 0;
        #pragma unroll
        for (int q = 0; q < 8; q++){ bl[q] = hist[base - q]; ssum += bl[q]; }
        unsigned cum = ssum;
        #pragma unroll
        for (int o = 1; o < 32; o <<= 1){
            unsigned vv = __shfl_up_sync(0xffffffffu, cum, o);
            if (lane >= o) cum += vv;
        }
        unsigned before = cum - ssum;
        if (before < remk && remk <= cum){
            unsigned c2 = before; int dig = base; unsigned r2 = 1; bool fnd = false;
            #pragma unroll
            for (int q = 0; q < 8; q++){
                if (!fnd && c2 + bl[q] >= remk){ dig = base - q; r2 = remk - c2; fnd = true; }
                c2 += bl[q];
            }
            sc[0] = (unsigned)dig; sc[1] = r2;
        }
    }
}

// ---------------- select core v2: exact top-20 of vals[0..4095]
//                  pass1 (aggregated atomics) -> candidate compaction -> small passes.
//                  key = (ordval<<32)|(4095-idx): value desc, index asc (jax top_k) ----------------
__device__ __forceinline__ void top20_select(
    unsigned* vals, unsigned* hist, unsigned long long* buf,
    unsigned long long* gtlist, unsigned* eqlow, unsigned* sc, int* out)
{
    int t = threadIdx.x, lane = t & 31;
    if (t == 0){ sc[2] = 0; sc[3] = 0; sc[4] = 0; }
    hist[t] = 0;
    __syncthreads();

    // pass 1: top byte histogram, warp-aggregated atomics
    for (int i = t; i < NPTS; i += 256){
        unsigned bin = vals[i] >> 24;
        unsigned m = __match_any_sync(0xffffffffu, bin);
        if ((m & ((1u << lane) - 1u)) == 0u) atomicAdd(&hist[bin], (unsigned)__popc(m));
    }
    __syncthreads();
    find_digit(hist, KNN, sc);
    __syncthreads();
    unsigned dig1 = sc[0], rem1 = sc[1];
    unsigned pfx1 = dig1 << 24;

    // compact all candidates with v >= dig1<<24 (superset of final top-20)
    for (int i = t; i < NPTS; i += 256){
        unsigned v = vals[i];
        bool p = (v >= pfx1);
        unsigned m = __ballot_sync(0xffffffffu, p);
        if (m){
            int leader = __ffs(m) - 1;
            unsigned pos = 0;
            if (lane == leader) pos = atomicAdd(&sc[2], (unsigned)__popc(m));
            pos = __shfl_sync(0xffffffffu, pos, leader);
            if (p){
                unsigned off = pos + (unsigned)__popc(m & ((1u << lane) - 1u));
                if (off < BUFSZ) buf[off] = ((unsigned long long)v << 32) | (unsigned)(NPTS - 1 - i);
            }
        }
    }
    __syncthreads();
    unsigned C = sc[2];
    unsigned prefix = pfx1, remk = rem1, thresh;

    if (C <= BUFSZ){
        #pragma unroll
        for (int d = 2; d >= 0; d--){
            __syncthreads();
            hist[t] = 0;
            __syncthreads();
            int sh = d*8;
            unsigned pmask = 0xFFFFFFFFu << (sh + 8);
            for (int i = t; i < (int)C; i += 256){
                unsigned v = (unsigned)(buf[i] >> 32);
                if ((v & pmask) == prefix) atomicAdd(&hist[(v >> sh) & 255u], 1u);
            }
            __syncthreads();
            find_digit(hist, remk, sc);
            __syncthreads();
            prefix |= sc[0] << sh;
            remk = sc[1];
        }
        thresh = prefix;
        for (int i = t; i < (int)C; i += 256){
            unsigned long long kk = buf[i];
            unsigned v = (unsigned)(kk >> 32);
            if (v > thresh){
                unsigned p = atomicAdd(&sc[3], 1u);
                if (p < 32) gtlist[p] = kk;
            } else if (v == thresh){
                unsigned p = atomicAdd(&sc[4], 1u);
                if (p < 64) eqlow[p] = (unsigned)(kk & 0xFFFFFFFFu);
            }
        }
    } else {
        // fallback: full scans (rare; correctness-guaranteed)
        #pragma unroll
        for (int d = 2; d >= 0; d--){
            __syncthreads();
            hist[t] = 0;
            __syncthreads();
            int sh = d*8;
            unsigned pmask = 0xFFFFFFFFu << (sh + 8);
            for (int i = t; i < NPTS; i += 256){
                unsigned v = vals[i];
                if ((v & pmask) == prefix) atomicAdd(&hist[(v >> sh) & 255u], 1u);
            }
            __syncthreads();
            find_digit(hist, remk, sc);
            __syncthreads();
            prefix |= sc[0] << sh;
            remk = sc[1];
        }
        thresh = prefix;
        for (int i = t; i < NPTS; i += 256){
            unsigned v = vals[i];
            if (v > thresh){
                unsigned p = atomicAdd(&sc[3], 1u);
                if (p < 32) gtlist[p] = ((unsigned long long)v << 32) | (unsigned)(NPTS - 1 - i);
            } else if (v == thresh){
                unsigned p = atomicAdd(&sc[4], 1u);
                if (p < 64) eqlow[p] = (unsigned)(NPTS - 1 - i);
            }
        }
    }
    __syncthreads();

    // warp 0 emits the 20 results in (value desc, index asc) order
    if (t < 32){
        unsigned cgt = sc[3];
        unsigned ceq = sc[4] < 64u ? sc[4] : 64u;
        unsigned tot = cgt + ceq;
        unsigned long long tk = (unsigned long long)thresh << 32;
        unsigned long long k0 = 0ull, k1 = 0ull;
        if ((unsigned)lane < tot)
            k0 = ((unsigned)lane < cgt) ? gtlist[lane] : (tk | eqlow[lane - cgt]);
        if ((unsigned)(lane + 32) < tot)
            k1 = tk | eqlow[lane + 32 - cgt];
        for (int it = 0; it < KNN; it++){
            unsigned long long r = (k0 > k1) ? k0 : k1;
            #pragma unroll
            for (int o = 16; o; o >>= 1){
                unsigned long long other = __shfl_xor_sync(0xffffffffu, r, o);
                if (other > r) r = other;
            }
            if (k0 == r) k0 = 0ull;
            else if (k1 == r) k1 = 0ull;
            if (lane == 0) out[it] = (NPTS - 1) - (int)(r & 0xFFFFFFFFu);
        }
    }
}

// ---------------- feature top-k: block per (row, batch) over g_pair ----------------
__global__ void k_topk(void)
{
    __shared__ __align__(16) unsigned int vals[NPTS];
    __shared__ unsigned int hist[256];
    __shared__ unsigned long long buf[BUFSZ];
    __shared__ unsigned long long gtlist[32];
    __shared__ unsigned int eqlow[64];
    __shared__ unsigned int sc[8];

    int t = threadIdx.x;
    int row = blockIdx.x, b = blockIdx.y;
    const float4* pr = (const float4*)(g_pair + (size_t)b*NPTS*NPTS + (size_t)row*NPTS);
    for (int j = t; j < NPTS/4; j += 256){
        float4 v = __ldg(&pr[j]);
        uint4 o; o.x = f2ord(v.x); o.y = f2ord(v.y); o.z = f2ord(v.z); o.w = f2ord(v.w);
        *(uint4*)&vals[4*j] = o;
    }
    int* out = g_idx1 + ((size_t)b*NPTS + row)*KNN;
    top20_select(vals, hist, buf, gtlist, eqlow, sc, out);
}

// ---------------- coordinate KNN, fused distance + select ----------------
__global__ void k_knn3(const float* __restrict__ x)
{
    __shared__ __align__(16) unsigned int vals[NPTS];
    __shared__ unsigned int hist[256];
    __shared__ unsigned long long buf[BUFSZ];
    __shared__ unsigned long long gtlist[32];
    __shared__ unsigned int eqlow[64];
    __shared__ unsigned int sc[8];

    int t = threadIdx.x;
    int row = blockIdx.x, b = blockIdx.y;
    const float* xb = x + (size_t)b*NPTS*3;
    const float* nn = g_nx + b*NPTS;
    float xr0 = xb[row*3+0], xr1 = xb[row*3+1], xr2 = xb[row*3+2];
    float rn = nn[row];
    for (int i = t; i < NPTS; i += 256){
        float m0 = __ldg(&xb[i*3+0]), m1 = __ldg(&xb[i*3+1]), m2 = __ldg(&xb[i*3+2]);
        float s = 0.f;
        s = fmaf(xr0, m0, s); s = fmaf(xr1, m1, s); s = fmaf(xr2, m2, s);
        vals[i] = f2ord(epi(s, rn, nn[i]));
    }
    int* out = g_idx2 + ((size_t)b*NPTS + row)*KNN;
    top20_select(vals, hist, buf, gtlist, eqlow, sc, out);
}

// ---------------- dg precompute: a = (Wc-Wd)@h, u = Wd@h; 8 groups per block ----------------
__global__ void k_dgpre(const float* __restrict__ wdg1)
{
    __shared__ float wct[64*64], wdt[64*64];
    __shared__ float hs[4][64];
    int t = threadIdx.x;
    for (int i = t; i < 4096; i += 256){
        int c = i>>6, k = i&63;
        float wc = wdg1[c*128 + k], wd = wdg1[c*128 + 64 + k];
        wdt[k*64+c] = wd;
        wct[k*64+c] = wc - wd;
    }
    __syncthreads();
    int lp = t>>6, c = t&63;
    float wa[64], wu[64];
    #pragma unroll
    for (int k = 0; k < 64; k++){ wa[k] = wct[k*64+c]; wu[k] = wdt[k*64+c]; }
    for (int g2 = 0; g2 < 8; g2++){
        int p = (blockIdx.x*8 + g2)*4 + lp;
        __syncthreads();
        hs[lp][c] = g_h[p*64+c];
        __syncthreads();
        float sa = 0.f, su = 0.f;
        #pragma unroll
        for (int k = 0; k < 64; k++){ float h = hs[lp][k]; sa += wa[k]*h; su += wu[k]*h; }
        g_a[p*64+c] = sa;
        g_u[p*64+c] = su;
    }
}

// ---------------- dg edge conv, two-phase ----------------
__global__ void k_dgedge(const float* __restrict__ w2,
                         const float* __restrict__ g1v, const float* __restrict__ b1v,
                         const float* __restrict__ g2v, const float* __restrict__ b2v)
{
    __shared__ float wt[4096];
    __shared__ float t1s[4][KNN][64];
    __shared__ float sg1[64], sb1[64], sg2[64], sb2[64];
    int t = threadIdx.x;
    for (int i = t; i < 4096; i += 256){ int c = i>>6, k = i&63; wt[k*64+c] = w2[i]; }
    if (t < 64){ sg1[t] = g1v[t]; sb1[t] = b1v[t]; sg2[t] = g2v[t]; sb2[t] = b2v[t]; }
    __syncthreads();
    int lp = t>>6, c = t&63;
    int p    = blockIdx.x*4 + lp;
    int base = (p >> 12) * NPTS;
    float ac = g_a[p*64+c];
    float G1 = sg1[c], B1 = sb1[c], G2 = sg2[c], B2 = sb2[c];
    const int* ip = &g_idx1[p*KNN];
    #pragma unroll 5
    for (int j = 0; j < KNN; j++){
        int m = ip[j];
        float v = (ac + g_u[(base+m)*64 + c]) * G1 + B1;
        t1s[lp][j][c] = lrelu(v);
    }
    float wr[64];
    #pragma unroll
    for (int k = 0; k < 64; k++) wr[k] = wt[k*64+c];
    __syncthreads();
    float mx = -3.4e38f;
    for (int j = 0; j < KNN; j++){
        const float4* tp4 = (const float4*)t1s[lp][j];
        float s = 0.f;
        #pragma unroll
        for (int k4 = 0; k4 < 16; k4++){
            float4 hv = tp4[k4];
            s += wr[4*k4+0]*hv.x + wr[4*k4+1]*hv.y + wr[4*k4+2]*hv.z + wr[4*k4+3]*hv.w;
        }
        s = lrelu(s*G2 + B2);
        mx = fmaxf(mx, s);
    }
    g_hdg[p*64+c] = mx;
}

// ---------------- sn branch: gather-max of per-point MLP output ----------------
__global__ void k_snmax()
{
    int t = threadIdx.x;
    int lp = t>>6, c = t&63;
    int p    = blockIdx.x*4 + lp;
    int base = (p >> 12) * NPTS;
    const int* ip = &g_idx2[p*KNN];
    float mx = -3.4e38f;
    for (int j = 0; j < KNN; j++){
        int m = ip[j];
        mx = fmaxf(mx, g_p2[(base+m)*64 + c]);
    }
    g_hsn[p*64+c] = mx;
}

// ---------------- conv5 GEMM ----------------
__global__ void k_conv5(const float* __restrict__ w5, const float* __restrict__ g5,
                        const float* __restrict__ b5, float* __restrict__ out)
{
    __shared__ float wt[64][68];
    __shared__ float ht[64][68];
    int t   = threadIdx.x;
    int co0 = blockIdx.y*64;
    int pt0 = blockIdx.x*64;
    int tr = (t>>4)<<2, tc = (t&15)<<2;
    float acc[4][4] = {{0.f,0.f,0.f,0.f},{0.f,0.f,0.f,0.f},{0.f,0.f,0.f,0.f},{0.f,0.f,0.f,0.f}};
    for (int kc = 0; kc < 2; kc++){
        __syncthreads();
        for (int i = t; i < 4096; i += 256){ int c = i>>6, k = i&63; wt[k][c] = w5[(co0+c)*128 + kc*64 + k]; }
        for (int i = t; i < 4096; i += 256){ int q = i>>6, k = i&63; ht[k][q] = g_h4[(size_t)(pt0+q)*128 + kc*64 + k]; }
        __syncthreads();
        #pragma unroll
        for (int k = 0; k < 64; k++){
            float4 wv = *(const float4*)&wt[k][tr];
            float4 hv = *(const float4*)&ht[k][tc];
            acc[0][0] += wv.x*hv.x; acc[0][1] += wv.x*hv.y; acc[0][2] += wv.x*hv.z; acc[0][3] += wv.x*hv.w;
            acc[1][0] += wv.y*hv.x; acc[1][1] += wv.y*hv.y; acc[1][2] += wv.y*hv.z; acc[1][3] += wv.y*hv.w;
            acc[2][0] += wv.z*hv.x; acc[2][1] += wv.z*hv.y; acc[2][2] += wv.z*hv.z; acc[2][3] += wv.z*hv.w;
            acc[3][0] += wv.w*hv.x; acc[3][1] += wv.w*hv.y; acc[3][2] += wv.w*hv.z; acc[3][3] += wv.w*hv.w;
        }
    }
    int bI = pt0 >> 12;
    int n0 = (pt0 + tc) & (NPTS-1);
    #pragma unroll
    for (int i = 0; i < 4; i++){
        int co = co0 + tr + i;
        float G = g5[co], Bv = b5[co];
        float4 o;
        o.x = lrelu(acc[i][0]*G + Bv);
        o.y = lrelu(acc[i][1]*G + Bv);
        o.z = lrelu(acc[i][2]*G + Bv);
        o.w = lrelu(acc[i][3]*G + Bv);
        *(float4*)&out[((size_t)bI*512 + co)*NPTS + n0] = o;
    }
}

// ---------------- launch ----------------
extern "C" void kernel_launch(void* const* d_in, const int* in_sizes, int n_in,
                              void* d_out, int out_size)
{
    const float* x    = (const float*)d_in[0];
    const float* w1   = (const float*)d_in[1];
    const float* g1   = (const float*)d_in[2];
    const float* b1   = (const float*)d_in[3];
    const float* w2   = (const float*)d_in[4];
    const float* g2   = (const float*)d_in[5];
    const float* b2   = (const float*)d_in[6];
    const float* wdg1 = (const float*)d_in[7];
    const float* gdg1 = (const float*)d_in[8];
    const float* bdg1 = (const float*)d_in[9];
    const float* wdg2 = (const float*)d_in[10];
    const float* gdg2 = (const float*)d_in[11];
    const float* bdg2 = (const float*)d_in[12];
    const float* wsn1 = (const float*)d_in[13];
    const float* gsn1 = (const float*)d_in[14];
    const float* bsn1 = (const float*)d_in[15];
    const float* wsn2 = (const float*)d_in[16];
    const float* gsn2 = (const float*)d_in[17];
    const float* bsn2 = (const float*)d_in[18];
    const float* w3   = (const float*)d_in[19];
    const float* g3   = (const float*)d_in[20];
    const float* b3   = (const float*)d_in[21];
    const float* w4   = (const float*)d_in[22];
    const float* g4   = (const float*)d_in[23];
    const float* b4   = (const float*)d_in[24];
    const float* w5   = (const float*)d_in[25];
    const float* g5   = (const float*)d_in[26];
    const float* b5   = (const float*)d_in[27];

    float* out  = (float*)d_out;

    // conv1 + conv2 (in-place) + norms
    k_conv1    <<<TOTPTS/4,  256>>>(x, w1, g1, b1);
    k_pconv<64><<<TOTPTS/32, 256>>>(0, w2, g2, b2);
    k_norms    <<<TOTPTS/256,256>>>(x);

    const int NTILE = 32*33/2;   // 528 upper-triangular 128x128 tiles
    // feature KNN (all batches, single launches)
    k_pair<<<dim3(NTILE, BB), 256>>>();
    k_topk<<<dim3(NPTS,  BB), 256>>>();
    // coordinate KNN (fused distance + select)
    k_knn3<<<dim3(NPTS,  BB), 256>>>(x);

    // dg branch
    k_dgpre <<<TOTPTS/32, 256>>>(wdg1);
    k_dgedge<<<TOTPTS/4,  256>>>(wdg2, gdg1, bdg1, gdg2, bdg2);

    // sn branch: per-point MLP then gather-max
    k_pconv<64><<<TOTPTS/32, 256>>>(1, wsn1, gsn1, bsn1);
    k_pconv<64><<<TOTPTS/32, 256>>>(2, wsn2, gsn2, bsn2);
    k_snmax    <<<TOTPTS/4,  256>>>();

    // head
    k_pconv<64> <<<TOTPTS/32, 256>>>(3, w3, g3, b3);
    k_pconv<128><<<TOTPTS/16, 256>>>(4, w4, g4, b4);
    k_conv5     <<<dim3(TOTPTS/64, 512/64), 256>>>(w5, g5, b5, out);
}